// round 13
// baseline (speedup 1.0000x reference)
#include <cuda_runtime.h>
#include <cstdint>

#define Bz    64
#define Sz    512
#define Hz    1024
#define NINz  128
#define NOUTz 128
#define GRIDz 128
#define NTH   512
#define NPC   8      // neurons per CTA per layer
#define NKC   16     // K-slices per CTA
#define KPT   64     // K per thread (Hz / NKC)

// Ping-pong hidden-state buffers, [parity][K][batch]. Device globals (no alloc allowed).
__device__ float g_h1[2][Hz][Bz];
__device__ float g_h2[2][Hz][Bz];
__device__ unsigned g_cnt;
__device__ unsigned g_gen;

// ---------------- packed fp32 helpers (fma.rn.f32x2 is PTX-only) ------------
__device__ __forceinline__ void fma2(unsigned long long& a,
                                     unsigned long long w,
                                     unsigned long long h) {
    asm("fma.rn.f32x2 %0, %1, %2, %0;" : "+l"(a) : "l"(w), "l"(h));
}
__device__ __forceinline__ unsigned long long pack2(float v) {
    unsigned long long r;
    asm("mov.b64 %0, {%1, %1};" : "=l"(r) : "f"(v));
    return r;
}

// ---------------- grid barrier (all 128 CTAs co-resident: 1 CTA/SM) ---------
__device__ __forceinline__ void gridbar() {
    __syncthreads();
    if (threadIdx.x == 0) {
        __threadfence();
        unsigned gen = *(volatile unsigned*)&g_gen;
        if (atomicAdd(&g_cnt, 1u) == GRIDz - 1u) {
            g_cnt = 0u;
            __threadfence();
            *(volatile unsigned*)&g_gen = gen + 1u;
        } else {
            while (*(volatile unsigned*)&g_gen == gen) { }
            __threadfence();
        }
    }
    __syncthreads();
}

// SMEM layout (floats):
//   sWtA[1024][16] : j<8 -> W_hh0 row (c8+j) ; j>=8 -> W_ih1 row (c8+j-8)
//   sWtB[1024][8]  : W_hh1 rows
//   sWx [128][8]   : W_ih0 rows
//   sCb [16]       : combined biases
//   sRed : 4096 float4, h-part partials, s-major layout (see writer)
//   sRedX: 2048 float4, x-part partials (old layout [j][Kc][lane2])
#define OFF_WTA 0
#define OFF_WTB (Hz * 16)
#define OFF_WX  (OFF_WTB + Hz * 8)
#define OFF_CB  (OFF_WX + NINz * 8)
#define OFF_RED (OFF_CB + 16)
#define OFF_REDX (OFF_RED + 4096 * 4)
#define SMEM_FLOATS (OFF_REDX + 2048 * 4)
#define SMEM_BYTES  (SMEM_FLOATS * 4)

__global__ __launch_bounds__(NTH, 1)
void rnn_persistent_kernel(const float* __restrict__ x,
                           const float* __restrict__ W_ih0,
                           const float* __restrict__ b_ih0,
                           const float* __restrict__ W_hh0,
                           const float* __restrict__ b_hh0,
                           const float* __restrict__ W_ih1,
                           const float* __restrict__ b_ih1,
                           const float* __restrict__ W_hh1,
                           const float* __restrict__ b_hh1,
                           const float* __restrict__ W_fc,
                           const float* __restrict__ b_fc,
                           float* __restrict__ out) {
    extern __shared__ float sm[];
    float*  sWtA  = sm + OFF_WTA;
    float*  sWtB  = sm + OFF_WTB;
    float*  sWx   = sm + OFF_WX;
    float*  sCb   = sm + OFF_CB;
    float4* sRed  = (float4*)(sm + OFF_RED);
    float4* sRedX = (float4*)(sm + OFF_REDX);

    const int c   = blockIdx.x;
    const int tid = threadIdx.x;
    const int c8  = c * NPC;

    // ---------------- load weight slices (once) ----------------
    #pragma unroll 1
    for (int j = 0; j < 16; ++j) {
        const float* src = (j < 8) ? (W_hh0 + (c8 + j) * Hz)
                                   : (W_ih1 + (c8 + j - 8) * Hz);
        for (int K = tid; K < Hz; K += NTH) sWtA[K * 16 + j] = src[K];
    }
    #pragma unroll 1
    for (int j = 0; j < 8; ++j) {
        const float* src = W_hh1 + (c8 + j) * Hz;
        for (int K = tid; K < Hz; K += NTH) sWtB[K * 8 + j] = src[K];
    }
    #pragma unroll 1
    for (int j = 0; j < 8; ++j) {
        const float* src = W_ih0 + (c8 + j) * NINz;
        for (int K = tid; K < NINz; K += NTH) sWx[K * 8 + j] = src[K];
    }
    if (tid < 16) {
        sCb[tid] = (tid < 8) ? (b_ih0[c8 + tid] + b_hh0[c8 + tid])
                             : (b_ih1[c8 + tid - 8] + b_hh1[c8 + tid - 8]);
    }
    // zero the "t = -1" slots this CTA owns (buffers hold junk across graph
    // replays). g_h2[0] too: phase 0's merged loop reads it (contributes 0).
    {
        int r = tid >> 6;        // 0..7
        int b = tid & 63;
        g_h1[1][c8 + r][b] = 0.f;
        g_h2[1][c8 + r][b] = 0.f;
        g_h2[0][c8 + r][b] = 0.f;
    }
    __syncthreads();
    gridbar();

    // Main-loop thread roles: lane4 -> batches 4*lane4..+3; half -> neuron
    // half (half0: L1 pairs {0,1} + L2 pairs {4,5} = weight cols 0-3 / 8-11;
    // half1: pairs {2,3} + {6,7} = cols 4-7 / 12-15); Kc -> 64-K slice.
    const int lane4 = tid & 15;
    const int half  = (tid >> 4) & 1;
    const int Kc    = tid >> 5;        // 0..15
    const int K0    = Kc << 6;         // * 64
    const int half4 = half * 4;
    // x-part roles (identical to the proven round-10 mapping)
    const int lane2 = tid & 31;        // batches 2*lane2, 2*lane2+1

    for (int p = 0; p <= Sz; ++p) {
        // aA[l][u]: L1 local pair l (global pair 2*half+l), batch 4*lane4+u
        // aB[l][u]: L2 local pair l (global pair 4+2*half+l)
        unsigned long long aA[2][4] = {{0,0,0,0},{0,0,0,0}};
        unsigned long long aB[2][4] = {{0,0,0,0},{0,0,0,0}};

        // Prefetch x rows early (overlaps the K loop). x-part uses lane2/Kc.
        float4 xva0, xva1, xvb0, xvb1;
        if (p < Sz) {
            const float* xa = x + (size_t)(2 * lane2) * (Sz * NINz)
                                + (size_t)p * NINz + Kc * 8;
            const float* xb = xa + (size_t)(Sz * NINz);
            xva0 = __ldg((const float4*)xa);
            xva1 = __ldg((const float4*)(xa + 4));
            xvb0 = __ldg((const float4*)xb);
            xvb1 = __ldg((const float4*)(xb + 4));
        }

        // Merged K loop: h1[p-1] x (W_hh0|W_ih1)  +  h2[p-2] x W_hh1
        {
            const float4* hp1 = (const float4*)(&g_h1[(p + 1) & 1][0][0]) + lane4;
            const float4* hp2 = (const float4*)(&g_h2[p & 1][0][0]) + lane4;
            #pragma unroll 4
            for (int K = K0; K < K0 + KPT; ++K) {
                float4 h1v = __ldcg(hp1 + K * 16);
                float4 h2v = __ldcg(hp2 + K * 16);
                unsigned long long q0 = pack2(h1v.x), q1 = pack2(h1v.y);
                unsigned long long q2 = pack2(h1v.z), q3 = pack2(h1v.w);
                unsigned long long r0 = pack2(h2v.x), r1 = pack2(h2v.y);
                unsigned long long r2 = pack2(h2v.z), r3 = pack2(h2v.w);

                ulonglong2 wA1 = *(const ulonglong2*)(sWtA + K * 16 + half4);
                ulonglong2 wA2 = *(const ulonglong2*)(sWtA + K * 16 + 8 + half4);
                ulonglong2 wB  = *(const ulonglong2*)(sWtB + K * 8 + half4);

                fma2(aA[0][0], wA1.x, q0); fma2(aA[0][1], wA1.x, q1);
                fma2(aA[0][2], wA1.x, q2); fma2(aA[0][3], wA1.x, q3);
                fma2(aA[1][0], wA1.y, q0); fma2(aA[1][1], wA1.y, q1);
                fma2(aA[1][2], wA1.y, q2); fma2(aA[1][3], wA1.y, q3);

                fma2(aB[0][0], wA2.x, q0); fma2(aB[0][1], wA2.x, q1);
                fma2(aB[0][2], wA2.x, q2); fma2(aB[0][3], wA2.x, q3);
                fma2(aB[1][0], wA2.y, q0); fma2(aB[1][1], wA2.y, q1);
                fma2(aB[1][2], wA2.y, q2); fma2(aB[1][3], wA2.y, q3);

                fma2(aB[0][0], wB.x, r0);  fma2(aB[0][1], wB.x, r1);
                fma2(aB[0][2], wB.x, r2);  fma2(aB[0][3], wB.x, r3);
                fma2(aB[1][0], wB.y, r0);  fma2(aB[1][1], wB.y, r1);
                fma2(aB[1][2], wB.y, r2);  fma2(aB[1][3], wB.y, r3);
            }
        }

        // x part: x[:,p,:] x W_ih0 -> L1 pairs 0..3, batches 2*lane2(+1).
        // Own accumulators; merged into the reduction via sRedX.
        unsigned long long xa0[4] = {0,0,0,0}, xa1[4] = {0,0,0,0};
        if (p < Sz) {
            float va[8] = { xva0.x, xva0.y, xva0.z, xva0.w,
                            xva1.x, xva1.y, xva1.z, xva1.w };
            float vb[8] = { xvb0.x, xvb0.y, xvb0.z, xvb0.w,
                            xvb1.x, xvb1.y, xvb1.z, xvb1.w };
            #pragma unroll
            for (int r = 0; r < 8; ++r) {
                int i = Kc * 8 + r;
                unsigned long long pa = pack2(va[r]);
                unsigned long long pb = pack2(vb[r]);
                const ulonglong2* w = (const ulonglong2*)(sWx + i * 8);
                ulonglong2 w0 = w[0], w1 = w[1];
                fma2(xa0[0], w0.x, pa); fma2(xa1[0], w0.x, pb);
                fma2(xa0[1], w0.y, pa); fma2(xa1[1], w0.y, pb);
                fma2(xa0[2], w1.x, pa); fma2(xa1[2], w1.x, pb);
                fma2(xa0[3], w1.y, pa); fma2(xa1[3], w1.y, pb);
            }
        }

        // -------- write partials: main (s-major, conflict-free) + x ---------
        #pragma unroll
        for (int l = 0; l < 2; ++l) {
            #pragma unroll
            for (int s = 0; s < 2; ++s) {
                float2 a0 = *(float2*)&aA[l][2 * s + 0];
                float2 a1 = *(float2*)&aA[l][2 * s + 1];
                sRed[((((0 * 2 + l) * 2 + s) * 16 + Kc) * 32) + half * 16 + lane4]
                    = make_float4(a0.x, a0.y, a1.x, a1.y);
                float2 b0 = *(float2*)&aB[l][2 * s + 0];
                float2 b1 = *(float2*)&aB[l][2 * s + 1];
                sRed[((((1 * 2 + l) * 2 + s) * 16 + Kc) * 32) + half * 16 + lane4]
                    = make_float4(b0.x, b0.y, b1.x, b1.y);
            }
        }
        #pragma unroll
        for (int j = 0; j < 4; ++j) {
            float2 f0 = *(float2*)&xa0[j];
            float2 f1 = *(float2*)&xa1[j];
            sRedX[(j * 16 + Kc) * 32 + lane2] = make_float4(f0.x, f0.y, f1.x, f1.y);
        }
        __syncthreads();

        // -------- reduce over Kc, add bias, tanh, publish -------------------
        {
            int jj = tid >> 6;          // global neuron pair 0..7
            int b2 = tid & 63;
            int region = jj >> 2;       // 0 = L1, 1 = L2
            int jl     = jj & 3;        // = 2*half + l of the writer
            int hsel   = jl >> 1;
            int l      = jl & 1;
            int lane4r = b2 >> 2;
            int qb     = b2 & 3;
            int s      = qb >> 1;
            int e      = qb & 1;
            const float2* rf = (const float2*)sRed;
            float sx = 0.f, sy = 0.f;
            #pragma unroll
            for (int q = 0; q < NKC; ++q) {
                float2 v = rf[(((((region * 2 + l) * 2 + s) * 16 + q) * 32)
                               + hsel * 16 + lane4r) * 2 + e];
                sx += v.x; sy += v.y;
            }
            if (jj < 4) {               // add x-part partials (L1 only)
                const float2* rx = (const float2*)sRedX;
                #pragma unroll
                for (int q = 0; q < NKC; ++q) {
                    float2 v = rx[((jj * 16 + q) * 32 + (b2 >> 1)) * 2 + (b2 & 1)];
                    sx += v.x; sy += v.y;
                }
            }
            sx += sCb[2 * jj];     sy += sCb[2 * jj + 1];
            sx = tanhf(sx);        sy = tanhf(sy);
            if (jj < 4) {          // layer-1 neurons
                if (p < Sz) {
                    int row = c8 + 2 * jj;
                    __stcg(&g_h1[p & 1][row][b2], sx);
                    __stcg(&g_h1[p & 1][row + 1][b2], sy);
                }
            } else {               // layer-2 neurons
                if (p >= 1) {
                    int row = c8 + 2 * (jj - 4);
                    __stcg(&g_h2[(p + 1) & 1][row][b2], sx);
                    __stcg(&g_h2[(p + 1) & 1][row + 1][b2], sy);
                }
            }
        }
        gridbar();   // includes __syncthreads: also protects sRed reuse
    }

    // ---------------- FC head: out[b][o] = h2[511] . W_fc[o] + b_fc[o] ------
    {
        const float* hL = &g_h2[1][0][0];     // h2[511] lives in parity 1
        int P  = c * 64 + (tid >> 3);         // output id 0..8191
        int kc = tid & 7;                     // 8-way K split
        int bb = P >> 7;
        int oo = P & 127;
        const float4* wf = (const float4*)(W_fc + oo * Hz + kc * 128);
        float s = 0.f;
        #pragma unroll 4
        for (int q = 0; q < 32; ++q) {
            float4 w4 = __ldg(wf + q);
            int k = kc * 128 + q * 4;
            s += __ldcg(hL + (k + 0) * Bz + bb) * w4.x;
            s += __ldcg(hL + (k + 1) * Bz + bb) * w4.y;
            s += __ldcg(hL + (k + 2) * Bz + bb) * w4.z;
            s += __ldcg(hL + (k + 3) * Bz + bb) * w4.w;
        }
        s += __shfl_down_sync(0xffffffffu, s, 4, 8);
        s += __shfl_down_sync(0xffffffffu, s, 2, 8);
        s += __shfl_down_sync(0xffffffffu, s, 1, 8);
        if (kc == 0) out[P] = s + b_fc[oo];
    }
}

extern "C" void kernel_launch(void* const* d_in, const int* in_sizes, int n_in,
                              void* d_out, int out_size) {
    const float* x     = (const float*)d_in[0];
    const float* W_ih0 = (const float*)d_in[1];
    const float* b_ih0 = (const float*)d_in[2];
    const float* W_hh0 = (const float*)d_in[3];
    const float* b_hh0 = (const float*)d_in[4];
    const float* W_ih1 = (const float*)d_in[5];
    const float* b_ih1 = (const float*)d_in[6];
    const float* W_hh1 = (const float*)d_in[7];
    const float* b_hh1 = (const float*)d_in[8];
    const float* W_fc  = (const float*)d_in[9];
    const float* b_fc  = (const float*)d_in[10];
    float* out = (float*)d_out;

    // >48KB dynamic smem needs the attribute; idempotent and capture-safe
    // (not a stream operation, so it is not recorded into the graph).
    cudaFuncSetAttribute(rnn_persistent_kernel,
                         cudaFuncAttributeMaxDynamicSharedMemorySize, SMEM_BYTES);

    rnn_persistent_kernel<<<GRIDz, NTH, SMEM_BYTES>>>(
        x, W_ih0, b_ih0, W_hh0, b_hh0,
        W_ih1, b_ih1, W_hh1, b_hh1, W_fc, b_fc, out);
}